// round 1
// baseline (speedup 1.0000x reference)
#include <cuda_runtime.h>
#include <cstdint>

#define HW 65536       // 256*256
#define CCH 256        // channels
#define NB 2           // batch

// Scratch (device globals — no allocations allowed)
__device__ float g_qkv[(size_t)NB * 768 * HW];   // 402 MB
__device__ float g_att[(size_t)NB * CCH * HW];   // 134 MB
__device__ float g_y  [(size_t)NB * CCH * HW];   // 134 MB

// ---------------------------------------------------------------------------
// Tiled SGEMM for 1x1 conv:  Y[b, o, s] = sum_c W[o,c] * X[b, c, s]
// K = 256 fixed, N = HW = 65536 per batch. Tile 64x64x16, 256 threads, 4x4/thread.
// grid: (HW/64, M/64, NB)
// ---------------------------------------------------------------------------
__global__ __launch_bounds__(256) void gemm1x1(const float* __restrict__ Wm,
                                               const float* __restrict__ X,
                                               float* __restrict__ Y) {
    const int b = blockIdx.z;
    const float* Xb = X + (size_t)b * CCH * HW;
    const int M64 = gridDim.y;            // M/64
    float* Yb = Y + (size_t)b * (M64 * 64) * HW;

    const int oBase = blockIdx.y * 64;
    const int sBase = blockIdx.x * 64;

    __shared__ float As[16][68];   // A transposed: As[k][o], pad 4 to dodge conflicts
    __shared__ float Bs[16][64];

    const int tid = threadIdx.x;
    const int tx = tid & 15;       // 0..15 -> 4 cols each
    const int ty = tid >> 4;       // 0..15 -> 4 rows each

    float acc[4][4] = {};

    for (int k0 = 0; k0 < 256; k0 += 16) {
        // Load A tile 64x16 (W rows oBase..+64, cols k0..+16), store transposed
        {
            int row = tid >> 2;            // 0..63
            int c4  = (tid & 3) * 4;       // 0,4,8,12
            float4 a = *reinterpret_cast<const float4*>(&Wm[(size_t)(oBase + row) * 256 + k0 + c4]);
            As[c4 + 0][row] = a.x;
            As[c4 + 1][row] = a.y;
            As[c4 + 2][row] = a.z;
            As[c4 + 3][row] = a.w;
        }
        // Load B tile 16x64 (X rows k0..+16, cols sBase..+64)
        {
            int row = tid >> 4;            // 0..15
            int c4  = (tid & 15) * 4;      // 0..60
            float4 v = *reinterpret_cast<const float4*>(&Xb[(size_t)(k0 + row) * HW + sBase + c4]);
            *reinterpret_cast<float4*>(&Bs[row][c4]) = v;
        }
        __syncthreads();

        #pragma unroll
        for (int kk = 0; kk < 16; kk++) {
            float4 av = *reinterpret_cast<const float4*>(&As[kk][ty * 4]);
            float4 bv = *reinterpret_cast<const float4*>(&Bs[kk][tx * 4]);
            acc[0][0] += av.x * bv.x; acc[0][1] += av.x * bv.y; acc[0][2] += av.x * bv.z; acc[0][3] += av.x * bv.w;
            acc[1][0] += av.y * bv.x; acc[1][1] += av.y * bv.y; acc[1][2] += av.y * bv.z; acc[1][3] += av.y * bv.w;
            acc[2][0] += av.z * bv.x; acc[2][1] += av.z * bv.y; acc[2][2] += av.z * bv.z; acc[2][3] += av.z * bv.w;
            acc[3][0] += av.w * bv.x; acc[3][1] += av.w * bv.y; acc[3][2] += av.w * bv.z; acc[3][3] += av.w * bv.w;
        }
        __syncthreads();
    }

    #pragma unroll
    for (int i = 0; i < 4; i++) {
        float4 v = make_float4(acc[i][0], acc[i][1], acc[i][2], acc[i][3]);
        *reinterpret_cast<float4*>(&Yb[(size_t)(oBase + ty * 4 + i) * HW + sBase + tx * 4]) = v;
    }
}

// ---------------------------------------------------------------------------
// Window attention + relative-position bias + residual.
// grid: (2048 windows, 16 heads), block: 64 threads (one per token).
// qkv layout: (B, 3*256, 256, 256), channel o = part*256 + head*16 + dd
// ---------------------------------------------------------------------------
__global__ __launch_bounds__(64) void attn_kernel(const float* __restrict__ qkv,
                                                  const float* __restrict__ x,
                                                  const float* __restrict__ bias_table,
                                                  float* __restrict__ att) {
    const int win = blockIdx.x;          // 0..2047
    const int h   = blockIdx.y;          // 0..15
    const int tid = threadIdx.x;         // token 0..63

    const int b   = win >> 10;           // 1024 windows per batch (32x32)
    const int rem = win & 1023;
    const int wy  = rem >> 5;
    const int wx  = rem & 31;
    const int yi  = wy * 8 + (tid >> 3);
    const int xi  = wx * 8 + (tid & 7);
    const int sp  = yi * 256 + xi;

    __shared__ float ks[16][64];
    __shared__ float vs[16][64];
    __shared__ float bs[225];

    for (int t = tid; t < 225; t += 64) bs[t] = bias_table[t * 16 + h];

    const float* base = qkv + ((size_t)b * 768 + h * 16) * HW + sp;
    float q[16];
    #pragma unroll
    for (int dd = 0; dd < 16; dd++) {
        q[dd]       = base[(size_t)dd * HW] * 0.25f;          // scale = 1/sqrt(16)
        ks[dd][tid] = base[(size_t)(256 + dd) * HW];
        vs[dd][tid] = base[(size_t)(512 + dd) * HW];
    }
    __syncthreads();

    const int yl = tid >> 3, xl = tid & 7;
    float dots[64];
    float mx = -1e30f;
    #pragma unroll
    for (int j = 0; j < 64; j++) {
        float s = 0.f;
        #pragma unroll
        for (int dd = 0; dd < 16; dd++) s += q[dd] * ks[dd][j];
        int yj = j >> 3, xj = j & 7;
        s += bs[(yl - yj + 7) * 15 + (xl - xj + 7)];
        dots[j] = s;
        mx = fmaxf(mx, s);
    }
    float sum = 0.f;
    #pragma unroll
    for (int j = 0; j < 64; j++) { dots[j] = __expf(dots[j] - mx); sum += dots[j]; }
    const float inv = 1.0f / sum;

    float o[16];
    #pragma unroll
    for (int dd = 0; dd < 16; dd++) o[dd] = 0.f;
    #pragma unroll
    for (int j = 0; j < 64; j++) {
        float p = dots[j];
        #pragma unroll
        for (int dd = 0; dd < 16; dd++) o[dd] += p * vs[dd][j];
    }

    const float* xb = x   + ((size_t)b * CCH + h * 16) * HW + sp;
    float*       ob = att + ((size_t)b * CCH + h * 16) * HW + sp;
    #pragma unroll
    for (int dd = 0; dd < 16; dd++)
        ob[(size_t)dd * HW] = o[dd] * inv + xb[(size_t)dd * HW];
}

// ---------------------------------------------------------------------------
// Fused: reflect-pad(+1 bottom/right) -> depthwise 3x3 (zero conv pad) -> BN
// Only the 256x256 region needed by the final crop is produced.
// grid: (8, 32, NB*CCH), block: (32, 8)
// ---------------------------------------------------------------------------
__global__ __launch_bounds__(256) void dwbn_kernel(const float* __restrict__ att,
                                                   const float* __restrict__ dw_w,
                                                   const float* __restrict__ gamma,
                                                   const float* __restrict__ beta,
                                                   const float* __restrict__ mean,
                                                   const float* __restrict__ var,
                                                   float* __restrict__ y) {
    const int c  = blockIdx.z & 255;
    const int b  = blockIdx.z >> 8;
    const int ox = blockIdx.x * 32 + threadIdx.x;
    const int oy = blockIdx.y * 8 + threadIdx.y;

    const float* in = att + ((size_t)b * CCH + c) * HW;
    float w[9];
    #pragma unroll
    for (int t = 0; t < 9; t++) w[t] = dw_w[c * 9 + t];

    float acc = 0.f;
    #pragma unroll
    for (int di = 0; di < 3; di++) {
        int r = oy + di - 1;
        if (r < 0) continue;            // conv zero-pad (top)
        if (r == 256) r = 254;          // reflect pad row
        #pragma unroll
        for (int dj = 0; dj < 3; dj++) {
            int cc = ox + dj - 1;
            if (cc < 0) continue;       // conv zero-pad (left)
            if (cc == 256) cc = 254;    // reflect pad col
            acc += w[di * 3 + dj] * __ldg(&in[r * 256 + cc]);
        }
    }
    const float invs = gamma[c] * rsqrtf(var[c] + 1e-5f);
    y[((size_t)b * CCH + c) * HW + oy * 256 + ox] = acc * invs + (beta[c] - mean[c] * invs);
}

// ---------------------------------------------------------------------------
extern "C" void kernel_launch(void* const* d_in, const int* in_sizes, int n_in,
                              void* d_out, int out_size) {
    const float* x          = (const float*)d_in[0];  // (2,256,256,256)
    const float* qkv_w      = (const float*)d_in[1];  // (768,256)
    const float* bias_table = (const float*)d_in[2];  // (225,16)
    const float* dw_w       = (const float*)d_in[3];  // (256,1,3,3)
    const float* bn_gamma   = (const float*)d_in[4];
    const float* bn_beta    = (const float*)d_in[5];
    const float* bn_mean    = (const float*)d_in[6];
    const float* bn_var     = (const float*)d_in[7];
    const float* pw_w       = (const float*)d_in[8];  // (256,256)
    float* out = (float*)d_out;                        // (2,256,256,256)

    float* qkv; cudaGetSymbolAddress((void**)&qkv, g_qkv);
    float* att; cudaGetSymbolAddress((void**)&att, g_att);
    float* yb;  cudaGetSymbolAddress((void**)&yb,  g_y);

    // 1) qkv 1x1 conv: (768 x 65536) per batch
    gemm1x1<<<dim3(HW / 64, 768 / 64, NB), 256>>>(qkv_w, x, qkv);

    // 2) windowed attention + bias + softmax + residual
    attn_kernel<<<dim3(2048, 16), 64>>>(qkv, x, bias_table, att);

    // 3) reflect-pad + depthwise 3x3 + BN
    dwbn_kernel<<<dim3(8, 32, NB * CCH), dim3(32, 8)>>>(att, dw_w, bn_gamma, bn_beta,
                                                        bn_mean, bn_var, yb);

    // 4) pointwise 1x1 conv -> d_out (crop is implicit)
    gemm1x1<<<dim3(HW / 64, 256 / 64, NB), 256>>>(pw_w, yb, out);
}

// round 3
// speedup vs baseline: 1.8370x; 1.8370x over previous
#include <cuda_runtime.h>
#include <cuda_bf16.h>
#include <cstdint>

#define HW 65536       // 256*256
#define CCH 256
#define NB 2

// ---------------------------------------------------------------------------
// Scratch (device globals — no allocations allowed)
// ---------------------------------------------------------------------------
__device__ float g_qkv[(size_t)NB * 768 * HW];
__device__ float g_att[(size_t)NB * CCH * HW];
__device__ __nv_bfloat16 g_xhi[(size_t)NB * CCH * HW];
__device__ __nv_bfloat16 g_xlo[(size_t)NB * CCH * HW];
__device__ __nv_bfloat16 g_yhi[(size_t)NB * CCH * HW];
__device__ __nv_bfloat16 g_ylo[(size_t)NB * CCH * HW];
__device__ __nv_bfloat16 g_wqhi[768 * 256], g_wqlo[768 * 256];
__device__ __nv_bfloat16 g_wphi[256 * 256], g_wplo[256 * 256];

// ---------------------------------------------------------------------------
// PTX helpers: ldmatrix + mma.sync (plain sm_80+ PTX — no 'a'-gated features)
// ---------------------------------------------------------------------------
__device__ __forceinline__ uint32_t smem_to_u32(const void* p) {
    uint32_t a;
    asm("{ .reg .u64 t; cvta.to.shared.u64 t, %1; cvt.u32.u64 %0, t; }" : "=r"(a) : "l"(p));
    return a;
}
__device__ __forceinline__ void ldsm_x4(uint32_t (&r)[4], uint32_t addr) {
    asm volatile("ldmatrix.sync.aligned.m8n8.x4.shared.b16 {%0,%1,%2,%3}, [%4];"
                 : "=r"(r[0]), "=r"(r[1]), "=r"(r[2]), "=r"(r[3]) : "r"(addr));
}
__device__ __forceinline__ void ldsm_x2_t(uint32_t (&r)[2], uint32_t addr) {
    asm volatile("ldmatrix.sync.aligned.m8n8.x2.trans.shared.b16 {%0,%1}, [%2];"
                 : "=r"(r[0]), "=r"(r[1]) : "r"(addr));
}
__device__ __forceinline__ void mma_bf16(float (&c)[4], const uint32_t (&a)[4],
                                         const uint32_t (&b)[2]) {
    asm volatile("mma.sync.aligned.m16n8k16.row.col.f32.bf16.bf16.f32 "
                 "{%0,%1,%2,%3}, {%4,%5,%6,%7}, {%8,%9}, {%0,%1,%2,%3};"
                 : "+f"(c[0]), "+f"(c[1]), "+f"(c[2]), "+f"(c[3])
                 : "r"(a[0]), "r"(a[1]), "r"(a[2]), "r"(a[3]), "r"(b[0]), "r"(b[1]));
}

// ---------------------------------------------------------------------------
// fp32 -> bf16 hi/lo split (vectorized by 4)
// ---------------------------------------------------------------------------
__global__ __launch_bounds__(256) void split_f32(const float* __restrict__ in,
                                                 __nv_bfloat16* __restrict__ hi,
                                                 __nv_bfloat16* __restrict__ lo,
                                                 size_t n4) {
    size_t i = (size_t)blockIdx.x * blockDim.x + threadIdx.x;
    if (i >= n4) return;
    float4 v = reinterpret_cast<const float4*>(in)[i];
    __nv_bfloat16 h0 = __float2bfloat16(v.x), h1 = __float2bfloat16(v.y);
    __nv_bfloat16 h2 = __float2bfloat16(v.z), h3 = __float2bfloat16(v.w);
    __nv_bfloat16 l0 = __float2bfloat16(v.x - __bfloat162float(h0));
    __nv_bfloat16 l1 = __float2bfloat16(v.y - __bfloat162float(h1));
    __nv_bfloat16 l2 = __float2bfloat16(v.z - __bfloat162float(h2));
    __nv_bfloat16 l3 = __float2bfloat16(v.w - __bfloat162float(h3));
    reinterpret_cast<__nv_bfloat162*>(hi)[i * 2]     = __nv_bfloat162(h0, h1);
    reinterpret_cast<__nv_bfloat162*>(hi)[i * 2 + 1] = __nv_bfloat162(h2, h3);
    reinterpret_cast<__nv_bfloat162*>(lo)[i * 2]     = __nv_bfloat162(l0, l1);
    reinterpret_cast<__nv_bfloat162*>(lo)[i * 2 + 1] = __nv_bfloat162(l2, l3);
}

// ---------------------------------------------------------------------------
// Split-bf16 tensor-core GEMM:  Y[b,o,s] = sum_c W[o,c] * X[b,c,s]
//   A = W [Mtot x 256] row-major bf16 (hi/lo).  B = X [256 x HW] row-major
//   (n contiguous) bf16 (hi/lo) — consumed via ldmatrix.trans.
// Tile: BM=128, BN=128, BK=32, 8 warps (2x4), warp tile 64x32.
// C = Ahi*Bhi + Alo*Bhi + Ahi*Blo  (fp32 accum)
// grid: (Mtot/128, HW/128, NB), block 256.
// ---------------------------------------------------------------------------
#define SA_STRIDE 80      // bytes per A row (32 bf16 padded to 40)
#define SB_STRIDE 272     // bytes per B row (128 bf16 padded to 136)
#define SA_HI 0
#define SA_LO 10240       // 128*80
#define SB_HI 20480
#define SB_LO 29184       // +32*272
#define SM_BYTES 37888

__global__ __launch_bounds__(256) void mma_gemm(const __nv_bfloat16* __restrict__ Whi,
                                                const __nv_bfloat16* __restrict__ Wlo,
                                                const __nv_bfloat16* __restrict__ Xhi,
                                                const __nv_bfloat16* __restrict__ Xlo,
                                                float* __restrict__ Y, int Mtot) {
    __shared__ __align__(128) char smem[SM_BYTES];
    const int tid  = threadIdx.x;
    const int wid  = tid >> 5;
    const int lane = tid & 31;

    const int oBase = blockIdx.x * 128;
    const int sBase = blockIdx.y * 128;
    const int b     = blockIdx.z;
    const __nv_bfloat16* XhiB = Xhi + (size_t)b * CCH * HW;
    const __nv_bfloat16* XloB = Xlo + (size_t)b * CCH * HW;
    float* Yb = Y + (size_t)b * Mtot * HW;

    const int wm = (wid >> 2) * 64;   // warp M offset within tile
    const int wn = (wid & 3) * 32;    // warp N offset within tile

    const uint32_t sb = smem_to_u32(smem);

    float acc[4][4][4];
    #pragma unroll
    for (int mi = 0; mi < 4; mi++)
        #pragma unroll
        for (int ni = 0; ni < 4; ni++)
            #pragma unroll
            for (int q = 0; q < 4; q++) acc[mi][ni][q] = 0.f;

    for (int chunk = 0; chunk < 8; chunk++) {
        const int kc = chunk * 32;

        // ---- A tiles: 128 rows x 32 bf16 (64B) each, hi & lo ----
        #pragma unroll
        for (int p = 0; p < 2; p++) {
            int idx = tid + p * 256;          // 0..511
            int r = idx >> 2, q = idx & 3;
            const size_t so = (size_t)(oBase + r) * 256 + kc + q * 8;
            *reinterpret_cast<uint4*>(smem + SA_HI + r * SA_STRIDE + q * 16) =
                *reinterpret_cast<const uint4*>(Whi + so);
            *reinterpret_cast<uint4*>(smem + SA_LO + r * SA_STRIDE + q * 16) =
                *reinterpret_cast<const uint4*>(Wlo + so);
        }
        // ---- B tiles: 32 rows x 128 bf16 (256B) each, hi & lo ----
        #pragma unroll
        for (int p = 0; p < 2; p++) {
            int idx = tid + p * 256;          // 0..511
            int k = idx >> 4, q = idx & 15;
            const size_t so = (size_t)(kc + k) * HW + sBase + q * 8;
            *reinterpret_cast<uint4*>(smem + SB_HI + k * SB_STRIDE + q * 16) =
                *reinterpret_cast<const uint4*>(XhiB + so);
            *reinterpret_cast<uint4*>(smem + SB_LO + k * SB_STRIDE + q * 16) =
                *reinterpret_cast<const uint4*>(XloB + so);
        }
        __syncthreads();

        const int ar   = wm + (lane & 15);            // A row for ldmatrix
        const int acolq = (lane >> 4) * 8;            // A col quadrant
        const int brow_base = lane & 15;              // B k-row for ldmatrix

        #pragma unroll
        for (int ks = 0; ks < 2; ks++) {
            #pragma unroll
            for (int p = 0; p < 3; p++) {
                const int aOff = (p == 1) ? SA_LO : SA_HI;
                const int bOff = (p == 2) ? SB_LO : SB_HI;
                uint32_t a[4][4];
                const int acol = ks * 16 + acolq;
                #pragma unroll
                for (int mi = 0; mi < 4; mi++)
                    ldsm_x4(a[mi], sb + aOff + (ar + mi * 16) * SA_STRIDE + acol * 2);
                uint32_t bfr[4][2];
                const int brow = ks * 16 + brow_base;
                #pragma unroll
                for (int ni = 0; ni < 4; ni++)
                    ldsm_x2_t(bfr[ni], sb + bOff + brow * SB_STRIDE + (wn + ni * 8) * 2);
                #pragma unroll
                for (int mi = 0; mi < 4; mi++)
                    #pragma unroll
                    for (int ni = 0; ni < 4; ni++)
                        mma_bf16(acc[mi][ni], a[mi], bfr[ni]);
            }
        }
        __syncthreads();
    }

    // ---- Epilogue: write fp32 ----
    const int groupID = lane >> 2;
    const int t4      = lane & 3;
    #pragma unroll
    for (int mi = 0; mi < 4; mi++) {
        #pragma unroll
        for (int ni = 0; ni < 4; ni++) {
            float* dst0 = Yb + (size_t)(oBase + wm + mi * 16 + groupID) * HW
                             + sBase + wn + ni * 8 + t4 * 2;
            *reinterpret_cast<float2*>(dst0) = make_float2(acc[mi][ni][0], acc[mi][ni][1]);
            *reinterpret_cast<float2*>(dst0 + 8 * HW) = make_float2(acc[mi][ni][2], acc[mi][ni][3]);
        }
    }
}

// ---------------------------------------------------------------------------
// Window attention + relative-position bias + residual.
// grid: (2048 windows, 16 heads), block: 64 threads (one per token).
// ---------------------------------------------------------------------------
__global__ __launch_bounds__(64) void attn_kernel(const float* __restrict__ qkv,
                                                  const float* __restrict__ x,
                                                  const float* __restrict__ bias_table,
                                                  float* __restrict__ att) {
    const int win = blockIdx.x;
    const int h   = blockIdx.y;
    const int tid = threadIdx.x;

    const int b   = win >> 10;
    const int rem = win & 1023;
    const int wy  = rem >> 5;
    const int wx  = rem & 31;
    const int yi  = wy * 8 + (tid >> 3);
    const int xi  = wx * 8 + (tid & 7);
    const int sp  = yi * 256 + xi;

    __shared__ float ks[16][64];
    __shared__ float vs[16][64];
    __shared__ float bs[225];

    for (int t = tid; t < 225; t += 64) bs[t] = bias_table[t * 16 + h];

    const float* base = qkv + ((size_t)b * 768 + h * 16) * HW + sp;
    float q[16];
    #pragma unroll
    for (int dd = 0; dd < 16; dd++) {
        q[dd]       = base[(size_t)dd * HW] * 0.25f;
        ks[dd][tid] = base[(size_t)(256 + dd) * HW];
        vs[dd][tid] = base[(size_t)(512 + dd) * HW];
    }
    __syncthreads();

    const int yl = tid >> 3, xl = tid & 7;
    float dots[64];
    float mx = -1e30f;
    #pragma unroll
    for (int j = 0; j < 64; j++) {
        float s = 0.f;
        #pragma unroll
        for (int dd = 0; dd < 16; dd++) s += q[dd] * ks[dd][j];
        int yj = j >> 3, xj = j & 7;
        s += bs[(yl - yj + 7) * 15 + (xl - xj + 7)];
        dots[j] = s;
        mx = fmaxf(mx, s);
    }
    float sum = 0.f;
    #pragma unroll
    for (int j = 0; j < 64; j++) { dots[j] = __expf(dots[j] - mx); sum += dots[j]; }
    const float inv = 1.0f / sum;

    float o[16];
    #pragma unroll
    for (int dd = 0; dd < 16; dd++) o[dd] = 0.f;
    #pragma unroll
    for (int j = 0; j < 64; j++) {
        float p = dots[j];
        #pragma unroll
        for (int dd = 0; dd < 16; dd++) o[dd] += p * vs[dd][j];
    }

    const float* xb = x   + ((size_t)b * CCH + h * 16) * HW + sp;
    float*       ob = att + ((size_t)b * CCH + h * 16) * HW + sp;
    #pragma unroll
    for (int dd = 0; dd < 16; dd++)
        ob[(size_t)dd * HW] = o[dd] * inv + xb[(size_t)dd * HW];
}

// ---------------------------------------------------------------------------
// reflect-pad -> depthwise 3x3 -> BN, emitting bf16 hi/lo for the pw GEMM.
// ---------------------------------------------------------------------------
__global__ __launch_bounds__(256) void dwbn_kernel(const float* __restrict__ att,
                                                   const float* __restrict__ dw_w,
                                                   const float* __restrict__ gamma,
                                                   const float* __restrict__ beta,
                                                   const float* __restrict__ mean,
                                                   const float* __restrict__ var,
                                                   __nv_bfloat16* __restrict__ yhi,
                                                   __nv_bfloat16* __restrict__ ylo) {
    const int c  = blockIdx.z & 255;
    const int b  = blockIdx.z >> 8;
    const int ox = blockIdx.x * 32 + threadIdx.x;
    const int oy = blockIdx.y * 8 + threadIdx.y;

    const float* in = att + ((size_t)b * CCH + c) * HW;
    float w[9];
    #pragma unroll
    for (int t = 0; t < 9; t++) w[t] = dw_w[c * 9 + t];

    float acc = 0.f;
    #pragma unroll
    for (int di = 0; di < 3; di++) {
        int r = oy + di - 1;
        if (r < 0) continue;
        if (r == 256) r = 254;
        #pragma unroll
        for (int dj = 0; dj < 3; dj++) {
            int cc = ox + dj - 1;
            if (cc < 0) continue;
            if (cc == 256) cc = 254;
            acc += w[di * 3 + dj] * __ldg(&in[r * 256 + cc]);
        }
    }
    const float invs = gamma[c] * rsqrtf(var[c] + 1e-5f);
    float y = acc * invs + (beta[c] - mean[c] * invs);
    __nv_bfloat16 h = __float2bfloat16(y);
    size_t idx = ((size_t)b * CCH + c) * HW + oy * 256 + ox;
    yhi[idx] = h;
    ylo[idx] = __float2bfloat16(y - __bfloat162float(h));
}

// ---------------------------------------------------------------------------
extern "C" void kernel_launch(void* const* d_in, const int* in_sizes, int n_in,
                              void* d_out, int out_size) {
    const float* x          = (const float*)d_in[0];
    const float* qkv_w      = (const float*)d_in[1];
    const float* bias_table = (const float*)d_in[2];
    const float* dw_w       = (const float*)d_in[3];
    const float* bn_gamma   = (const float*)d_in[4];
    const float* bn_beta    = (const float*)d_in[5];
    const float* bn_mean    = (const float*)d_in[6];
    const float* bn_var     = (const float*)d_in[7];
    const float* pw_w       = (const float*)d_in[8];
    float* out = (float*)d_out;

    float* qkv; cudaGetSymbolAddress((void**)&qkv, g_qkv);
    float* att; cudaGetSymbolAddress((void**)&att, g_att);
    __nv_bfloat16 *xhi, *xlo, *yhi, *ylo, *wqhi, *wqlo, *wphi, *wplo;
    cudaGetSymbolAddress((void**)&xhi, g_xhi);
    cudaGetSymbolAddress((void**)&xlo, g_xlo);
    cudaGetSymbolAddress((void**)&yhi, g_yhi);
    cudaGetSymbolAddress((void**)&ylo, g_ylo);
    cudaGetSymbolAddress((void**)&wqhi, g_wqhi);
    cudaGetSymbolAddress((void**)&wqlo, g_wqlo);
    cudaGetSymbolAddress((void**)&wphi, g_wphi);
    cudaGetSymbolAddress((void**)&wplo, g_wplo);

    // 0) bf16 hi/lo splits
    {
        size_t n4 = ((size_t)NB * CCH * HW) / 4;
        split_f32<<<(unsigned)((n4 + 255) / 256), 256>>>(x, xhi, xlo, n4);
        size_t wq4 = (768 * 256) / 4;
        split_f32<<<(unsigned)((wq4 + 255) / 256), 256>>>(qkv_w, wqhi, wqlo, wq4);
        size_t wp4 = (256 * 256) / 4;
        split_f32<<<(unsigned)((wp4 + 255) / 256), 256>>>(pw_w, wphi, wplo, wp4);
    }

    // 1) qkv 1x1 conv (tensor cores): 768 x 65536 per batch
    mma_gemm<<<dim3(768 / 128, HW / 128, NB), 256>>>(wqhi, wqlo, xhi, xlo, qkv, 768);

    // 2) windowed attention + bias + softmax + residual
    attn_kernel<<<dim3(2048, 16), 64>>>(qkv, x, bias_table, att);

    // 3) reflect-pad + depthwise 3x3 + BN -> bf16 hi/lo
    dwbn_kernel<<<dim3(8, 32, NB * CCH), dim3(32, 8)>>>(att, dw_w, bn_gamma, bn_beta,
                                                        bn_mean, bn_var, yhi, ylo);

    // 4) pointwise 1x1 conv (tensor cores) -> d_out
    mma_gemm<<<dim3(256 / 128, HW / 128, NB), 256>>>(wphi, wplo, yhi, ylo, out, 256);
}

// round 4
// speedup vs baseline: 2.0555x; 1.1189x over previous
#include <cuda_runtime.h>
#include <cuda_bf16.h>
#include <cstdint>

#define HW 65536       // 256*256
#define CCH 256
#define NB 2

// ---------------------------------------------------------------------------
// Scratch (device globals — no allocations allowed)
// ---------------------------------------------------------------------------
__device__ uint32_t g_qkv[(size_t)NB * 768 * HW];   // packed bf16 hi|lo, window layout
__device__ float g_att[(size_t)NB * CCH * HW];
__device__ __nv_bfloat16 g_xhi[(size_t)NB * CCH * HW];
__device__ __nv_bfloat16 g_xlo[(size_t)NB * CCH * HW];
__device__ __nv_bfloat16 g_yhi[(size_t)NB * CCH * HW];
__device__ __nv_bfloat16 g_ylo[(size_t)NB * CCH * HW];
__device__ __nv_bfloat16 g_wqhi[768 * 256], g_wqlo[768 * 256];
__device__ __nv_bfloat16 g_wphi[256 * 256], g_wplo[256 * 256];

// ---------------------------------------------------------------------------
// PTX helpers (plain sm_80+ PTX)
// ---------------------------------------------------------------------------
__device__ __forceinline__ uint32_t smem_to_u32(const void* p) {
    uint32_t a;
    asm("{ .reg .u64 t; cvta.to.shared.u64 t, %1; cvt.u32.u64 %0, t; }" : "=r"(a) : "l"(p));
    return a;
}
__device__ __forceinline__ void ldsm_x4(uint32_t (&r)[4], uint32_t addr) {
    asm volatile("ldmatrix.sync.aligned.m8n8.x4.shared.b16 {%0,%1,%2,%3}, [%4];"
                 : "=r"(r[0]), "=r"(r[1]), "=r"(r[2]), "=r"(r[3]) : "r"(addr));
}
__device__ __forceinline__ void ldsm_x2_t(uint32_t (&r)[2], uint32_t addr) {
    asm volatile("ldmatrix.sync.aligned.m8n8.x2.trans.shared.b16 {%0,%1}, [%2];"
                 : "=r"(r[0]), "=r"(r[1]) : "r"(addr));
}
__device__ __forceinline__ void mma_bf16(float (&c)[4], const uint32_t (&a)[4],
                                         const uint32_t (&b)[2]) {
    asm volatile("mma.sync.aligned.m16n8k16.row.col.f32.bf16.bf16.f32 "
                 "{%0,%1,%2,%3}, {%4,%5,%6,%7}, {%8,%9}, {%0,%1,%2,%3};"
                 : "+f"(c[0]), "+f"(c[1]), "+f"(c[2]), "+f"(c[3])
                 : "r"(a[0]), "r"(a[1]), "r"(a[2]), "r"(a[3]), "r"(b[0]), "r"(b[1]));
}
__device__ __forceinline__ void cp_async16(uint32_t sm, const void* g) {
    asm volatile("cp.async.cg.shared.global [%0], [%1], 16;" :: "r"(sm), "l"(g));
}
__device__ __forceinline__ uint32_t packsplit(float v) {
    __nv_bfloat16 h = __float2bfloat16(v);
    __nv_bfloat16 l = __float2bfloat16(v - __bfloat162float(h));
    return (uint32_t)__bfloat16_as_ushort(h) | ((uint32_t)__bfloat16_as_ushort(l) << 16);
}

// ---------------------------------------------------------------------------
// fp32 -> bf16 hi/lo split
// ---------------------------------------------------------------------------
__global__ __launch_bounds__(256) void split_f32(const float* __restrict__ in,
                                                 __nv_bfloat16* __restrict__ hi,
                                                 __nv_bfloat16* __restrict__ lo,
                                                 size_t n4) {
    size_t i = (size_t)blockIdx.x * blockDim.x + threadIdx.x;
    if (i >= n4) return;
    float4 v = reinterpret_cast<const float4*>(in)[i];
    __nv_bfloat16 h0 = __float2bfloat16(v.x), h1 = __float2bfloat16(v.y);
    __nv_bfloat16 h2 = __float2bfloat16(v.z), h3 = __float2bfloat16(v.w);
    __nv_bfloat16 l0 = __float2bfloat16(v.x - __bfloat162float(h0));
    __nv_bfloat16 l1 = __float2bfloat16(v.y - __bfloat162float(h1));
    __nv_bfloat16 l2 = __float2bfloat16(v.z - __bfloat162float(h2));
    __nv_bfloat16 l3 = __float2bfloat16(v.w - __bfloat162float(h3));
    reinterpret_cast<__nv_bfloat162*>(hi)[i * 2]     = __nv_bfloat162(h0, h1);
    reinterpret_cast<__nv_bfloat162*>(hi)[i * 2 + 1] = __nv_bfloat162(h2, h3);
    reinterpret_cast<__nv_bfloat162*>(lo)[i * 2]     = __nv_bfloat162(l0, l1);
    reinterpret_cast<__nv_bfloat162*>(lo)[i * 2 + 1] = __nv_bfloat162(l2, l3);
}

// ---------------------------------------------------------------------------
// cp.async double-buffered split-bf16 tensor-core GEMM.
// MODE 0: write fp32 channel-major.  MODE 1: write packed u32 window layout.
// ---------------------------------------------------------------------------
#define SA_STRIDE 80
#define SB_STRIDE 272
#define SA_HI 0
#define SA_LO 10240
#define SB_HI 20480
#define SB_LO 29184
#define STAGE 37888
#define SM_TOT (2 * STAGE)

template<int MODE>
__global__ __launch_bounds__(256) void mma_gemm(const __nv_bfloat16* __restrict__ Whi,
                                                const __nv_bfloat16* __restrict__ Wlo,
                                                const __nv_bfloat16* __restrict__ Xhi,
                                                const __nv_bfloat16* __restrict__ Xlo,
                                                void* __restrict__ Yv, int Mtot) {
    extern __shared__ __align__(128) char smem[];
    const int tid  = threadIdx.x;
    const int wid  = tid >> 5;
    const int lane = tid & 31;
    const int g    = lane >> 2;
    const int t4   = lane & 3;

    const int oBase = blockIdx.x * 128;
    const int sBase = blockIdx.y * 128;
    const int b     = blockIdx.z;
    const __nv_bfloat16* XhiB = Xhi + (size_t)b * CCH * HW;
    const __nv_bfloat16* XloB = Xlo + (size_t)b * CCH * HW;

    const int wm = (wid >> 2) * 64;
    const int wn = (wid & 3) * 32;
    const uint32_t sb = smem_to_u32(smem);

    const int ar_ = tid >> 2, aq_ = tid & 3;
    const int bk_ = tid >> 4, bq_ = tid & 15;

    float acc[4][4][4];
    #pragma unroll
    for (int mi = 0; mi < 4; mi++)
        #pragma unroll
        for (int ni = 0; ni < 4; ni++)
            #pragma unroll
            for (int q = 0; q < 4; q++) acc[mi][ni][q] = 0.f;

    // issue loads for a chunk into buffer (chunk&1)
    auto issue = [&](int chunk) {
        const int kc = chunk * 32;
        const uint32_t st = sb + (chunk & 1) * STAGE;
        #pragma unroll
        for (int p = 0; p < 2; p++) {
            int r = ar_ + p * 64;
            const size_t so = (size_t)(oBase + r) * 256 + kc + aq_ * 8;
            cp_async16(st + SA_HI + r * SA_STRIDE + aq_ * 16, Whi + so);
            cp_async16(st + SA_LO + r * SA_STRIDE + aq_ * 16, Wlo + so);
            int k = bk_ + p * 16;
            const size_t sbo = (size_t)(kc + k) * HW + sBase + bq_ * 8;
            cp_async16(st + SB_HI + k * SB_STRIDE + bq_ * 16, XhiB + sbo);
            cp_async16(st + SB_LO + k * SB_STRIDE + bq_ * 16, XloB + sbo);
        }
        asm volatile("cp.async.commit_group;");
    };

    issue(0);
    for (int chunk = 0; chunk < 8; chunk++) {
        if (chunk < 7) {
            issue(chunk + 1);
            asm volatile("cp.async.wait_group 1;");
        } else {
            asm volatile("cp.async.wait_group 0;");
        }
        __syncthreads();

        const uint32_t smu = sb + (chunk & 1) * STAGE;
        const int ar    = wm + (lane & 15);
        const int acolq = (lane >> 4) * 8;
        const int brow_base = lane & 15;

        #pragma unroll
        for (int ks = 0; ks < 2; ks++) {
            #pragma unroll
            for (int p = 0; p < 3; p++) {
                const int aOff = (p == 1) ? SA_LO : SA_HI;
                const int bOff = (p == 2) ? SB_LO : SB_HI;
                uint32_t a[4][4];
                const int acol = ks * 16 + acolq;
                #pragma unroll
                for (int mi = 0; mi < 4; mi++)
                    ldsm_x4(a[mi], smu + aOff + (ar + mi * 16) * SA_STRIDE + acol * 2);
                uint32_t bfr[4][2];
                const int brow = ks * 16 + brow_base;
                #pragma unroll
                for (int ni = 0; ni < 4; ni++)
                    ldsm_x2_t(bfr[ni], smu + bOff + brow * SB_STRIDE + (wn + ni * 8) * 2);
                #pragma unroll
                for (int mi = 0; mi < 4; mi++)
                    #pragma unroll
                    for (int ni = 0; ni < 4; ni++)
                        mma_bf16(acc[mi][ni], a[mi], bfr[ni]);
            }
        }
        __syncthreads();
    }

    if (MODE == 0) {
        float* Yb = (float*)Yv + (size_t)b * Mtot * HW;
        #pragma unroll
        for (int mi = 0; mi < 4; mi++) {
            #pragma unroll
            for (int ni = 0; ni < 4; ni++) {
                float* dst0 = Yb + (size_t)(oBase + wm + mi * 16 + g) * HW
                                 + sBase + wn + ni * 8 + t4 * 2;
                *reinterpret_cast<float2*>(dst0) = make_float2(acc[mi][ni][0], acc[mi][ni][1]);
                *reinterpret_cast<float2*>(dst0 + 8 * HW) = make_float2(acc[mi][ni][2], acc[mi][ni][3]);
            }
        }
    } else {
        uint32_t* U = (uint32_t*)Yv;
        #pragma unroll
        for (int mi = 0; mi < 4; mi++) {
            #pragma unroll
            for (int ni = 0; ni < 4; ni++) {
                const int o0   = oBase + wm + mi * 16 + g;
                const int part = o0 >> 8;
                const int head = (o0 >> 4) & 15;
                const int dd   = o0 & 15;
                const int s0   = sBase + wn + ni * 8 + t4 * 2;
                const int y    = s0 >> 8, xx = s0 & 255;
                const int win  = b * 1024 + (y >> 3) * 32 + (xx >> 3);
                const int tok  = (y & 7) * 8 + (xx & 7);
                const size_t base = ((size_t)(win * 3 + part) * 16 + head) * 1024 + tok;
                uint2 v0 = make_uint2(packsplit(acc[mi][ni][0]), packsplit(acc[mi][ni][1]));
                uint2 v1 = make_uint2(packsplit(acc[mi][ni][2]), packsplit(acc[mi][ni][3]));
                *reinterpret_cast<uint2*>(U + base + (size_t)dd * 64)       = v0;
                *reinterpret_cast<uint2*>(U + base + (size_t)(dd + 8) * 64) = v1;
            }
        }
    }
}

// ---------------------------------------------------------------------------
// Tensor-core window attention.  One block = one (window, head), 2 warps.
// qkv packed u32 (hi|lo<<16), layout [win][part][head][d(16)][tok(64)].
// Warp w handles q rows [32w, 32w+32).
// ---------------------------------------------------------------------------
__global__ __launch_bounds__(64) void attn_mma(const uint32_t* __restrict__ qkvU,
                                               const float* __restrict__ x,
                                               const float* __restrict__ bias_table,
                                               float* __restrict__ att) {
    const int win = blockIdx.x;
    const int h   = blockIdx.y;
    const int tid = threadIdx.x;
    const int w   = tid >> 5;
    const int lane = tid & 31;
    const int g = lane >> 2, t = lane & 3;

    __shared__ float bs[225];
    for (int i = tid; i < 225; i += 64) bs[i] = bias_table[i * 16 + h];
    __syncthreads();

    const uint32_t* Q = qkvU + ((size_t)(win * 3) * 16 + h) * 1024;
    const uint32_t* K = Q + 16 * 1024;
    const uint32_t* V = Q + 32 * 1024;

    // ---- Q A-fragments (2 m-tiles) ----
    uint32_t ahi[2][4], alo[2][4];
    #pragma unroll
    for (int mi = 0; mi < 2; mi++) {
        const int tokm = w * 32 + mi * 16;
        #pragma unroll
        for (int r = 0; r < 4; r++) {
            const int m  = tokm + g + ((r & 1) ? 8 : 0);
            const int k0 = t * 2 + ((r >= 2) ? 8 : 0);
            uint32_t u0 = Q[k0 * 64 + m];
            uint32_t u1 = Q[(k0 + 1) * 64 + m];
            ahi[mi][r] = __byte_perm(u0, u1, 0x5410);
            alo[mi][r] = __byte_perm(u0, u1, 0x7632);
        }
    }
    // ---- K B-fragments (8 n-tiles) ----
    uint32_t bhi[8][2], blo[8][2];
    #pragma unroll
    for (int ni = 0; ni < 8; ni++) {
        const int n = ni * 8 + g;
        #pragma unroll
        for (int r = 0; r < 2; r++) {
            const int k0 = t * 2 + r * 8;
            uint32_t u0 = K[k0 * 64 + n];
            uint32_t u1 = K[(k0 + 1) * 64 + n];
            bhi[ni][r] = __byte_perm(u0, u1, 0x5410);
            blo[ni][r] = __byte_perm(u0, u1, 0x7632);
        }
    }

    // ---- QK^T (split: hi*hi + lo*hi + hi*lo) ----
    float C[2][8][4];
    #pragma unroll
    for (int mi = 0; mi < 2; mi++)
        #pragma unroll
        for (int ni = 0; ni < 8; ni++) {
            C[mi][ni][0] = C[mi][ni][1] = C[mi][ni][2] = C[mi][ni][3] = 0.f;
            mma_bf16(C[mi][ni], ahi[mi], bhi[ni]);
            mma_bf16(C[mi][ni], alo[mi], bhi[ni]);
            mma_bf16(C[mi][ni], ahi[mi], blo[ni]);
        }

    // ---- scale + bias + softmax (rows in C-fragments) ----
    #pragma unroll
    for (int mi = 0; mi < 2; mi++) {
        const int yl0 = w * 4 + mi * 2;
        float m0 = -1e30f, m1 = -1e30f;
        #pragma unroll
        for (int ni = 0; ni < 8; ni++) {
            const int cb0 = g - t * 2 + 7;
            C[mi][ni][0] = C[mi][ni][0] * 0.25f + bs[(yl0 - ni + 7) * 15 + cb0];
            C[mi][ni][1] = C[mi][ni][1] * 0.25f + bs[(yl0 - ni + 7) * 15 + cb0 - 1];
            C[mi][ni][2] = C[mi][ni][2] * 0.25f + bs[(yl0 + 1 - ni + 7) * 15 + cb0];
            C[mi][ni][3] = C[mi][ni][3] * 0.25f + bs[(yl0 + 1 - ni + 7) * 15 + cb0 - 1];
            m0 = fmaxf(m0, fmaxf(C[mi][ni][0], C[mi][ni][1]));
            m1 = fmaxf(m1, fmaxf(C[mi][ni][2], C[mi][ni][3]));
        }
        m0 = fmaxf(m0, __shfl_xor_sync(0xffffffffu, m0, 1));
        m0 = fmaxf(m0, __shfl_xor_sync(0xffffffffu, m0, 2));
        m1 = fmaxf(m1, __shfl_xor_sync(0xffffffffu, m1, 1));
        m1 = fmaxf(m1, __shfl_xor_sync(0xffffffffu, m1, 2));
        float s0 = 0.f, s1 = 0.f;
        #pragma unroll
        for (int ni = 0; ni < 8; ni++) {
            C[mi][ni][0] = __expf(C[mi][ni][0] - m0);
            C[mi][ni][1] = __expf(C[mi][ni][1] - m0);
            C[mi][ni][2] = __expf(C[mi][ni][2] - m1);
            C[mi][ni][3] = __expf(C[mi][ni][3] - m1);
            s0 += C[mi][ni][0] + C[mi][ni][1];
            s1 += C[mi][ni][2] + C[mi][ni][3];
        }
        s0 += __shfl_xor_sync(0xffffffffu, s0, 1);
        s0 += __shfl_xor_sync(0xffffffffu, s0, 2);
        s1 += __shfl_xor_sync(0xffffffffu, s1, 1);
        s1 += __shfl_xor_sync(0xffffffffu, s1, 2);
        const float iv0 = 1.f / s0, iv1 = 1.f / s1;
        #pragma unroll
        for (int ni = 0; ni < 8; ni++) {
            C[mi][ni][0] *= iv0; C[mi][ni][1] *= iv0;
            C[mi][ni][2] *= iv1; C[mi][ni][3] *= iv1;
        }
    }

    // ---- P @ V (split P and V) ----
    float O[2][2][4];
    #pragma unroll
    for (int mi = 0; mi < 2; mi++)
        #pragma unroll
        for (int nd = 0; nd < 2; nd++)
            O[mi][nd][0] = O[mi][nd][1] = O[mi][nd][2] = O[mi][nd][3] = 0.f;

    #pragma unroll
    for (int kk = 0; kk < 4; kk++) {
        uint32_t vhi[2][2], vlo[2][2];
        #pragma unroll
        for (int nd = 0; nd < 2; nd++)
            #pragma unroll
            for (int r = 0; r < 2; r++) {
                const uint32_t* vp = V + (nd * 8 + g) * 64 + kk * 16 + t * 2 + r * 8;
                uint32_t u0 = vp[0], u1 = vp[1];
                vhi[nd][r] = __byte_perm(u0, u1, 0x5410);
                vlo[nd][r] = __byte_perm(u0, u1, 0x7632);
            }
        #pragma unroll
        for (int mi = 0; mi < 2; mi++) {
            uint32_t phi[4], plo[4];
            #pragma unroll
            for (int r = 0; r < 4; r++) {
                const int ni = 2 * kk + (r >> 1);
                const float e  = C[mi][ni][(r & 1) * 2];
                const float o_ = C[mi][ni][(r & 1) * 2 + 1];
                uint32_t hp;
                asm("cvt.rn.bf16x2.f32 %0, %1, %2;" : "=r"(hp) : "f"(o_), "f"(e));
                const float eh = __uint_as_float((hp & 0xFFFFu) << 16);
                const float oh = __uint_as_float(hp & 0xFFFF0000u);
                uint32_t lp;
                asm("cvt.rn.bf16x2.f32 %0, %1, %2;" : "=r"(lp) : "f"(o_ - oh), "f"(e - eh));
                phi[r] = hp; plo[r] = lp;
            }
            #pragma unroll
            for (int nd = 0; nd < 2; nd++) {
                mma_bf16(O[mi][nd], phi, vhi[nd]);
                mma_bf16(O[mi][nd], plo, vhi[nd]);
                mma_bf16(O[mi][nd], phi, vlo[nd]);
            }
        }
    }

    // ---- residual + store to channel-major fp32 ----
    const int bW = win >> 10, loc = win & 1023;
    const int wy = loc >> 5, wx = loc & 31;
    #pragma unroll
    for (int mi = 0; mi < 2; mi++) {
        const int row0 = w * 4 + mi * 2;
        const int sp0 = (wy * 8 + row0) * 256 + wx * 8 + g;
        const int sp1 = sp0 + 256;
        #pragma unroll
        for (int nd = 0; nd < 2; nd++) {
            const int d0 = nd * 8 + t * 2;
            const size_t c0 = ((size_t)bW * 256 + h * 16 + d0) * HW;
            const size_t c1 = c0 + HW;
            att[c0 + sp0] = O[mi][nd][0] + x[c0 + sp0];
            att[c1 + sp0] = O[mi][nd][1] + x[c1 + sp0];
            att[c0 + sp1] = O[mi][nd][2] + x[c0 + sp1];
            att[c1 + sp1] = O[mi][nd][3] + x[c1 + sp1];
        }
    }
}

// ---------------------------------------------------------------------------
// reflect-pad -> depthwise 3x3 -> BN -> bf16 hi/lo
// ---------------------------------------------------------------------------
__global__ __launch_bounds__(256) void dwbn_kernel(const float* __restrict__ att,
                                                   const float* __restrict__ dw_w,
                                                   const float* __restrict__ gamma,
                                                   const float* __restrict__ beta,
                                                   const float* __restrict__ mean,
                                                   const float* __restrict__ var,
                                                   __nv_bfloat16* __restrict__ yhi,
                                                   __nv_bfloat16* __restrict__ ylo) {
    const int c  = blockIdx.z & 255;
    const int b  = blockIdx.z >> 8;
    const int ox = blockIdx.x * 32 + threadIdx.x;
    const int oy = blockIdx.y * 8 + threadIdx.y;

    const float* in = att + ((size_t)b * CCH + c) * HW;
    float w[9];
    #pragma unroll
    for (int tt = 0; tt < 9; tt++) w[tt] = dw_w[c * 9 + tt];

    float acc = 0.f;
    #pragma unroll
    for (int di = 0; di < 3; di++) {
        int r = oy + di - 1;
        if (r < 0) continue;
        if (r == 256) r = 254;
        #pragma unroll
        for (int dj = 0; dj < 3; dj++) {
            int cc = ox + dj - 1;
            if (cc < 0) continue;
            if (cc == 256) cc = 254;
            acc += w[di * 3 + dj] * __ldg(&in[r * 256 + cc]);
        }
    }
    const float invs = gamma[c] * rsqrtf(var[c] + 1e-5f);
    float y = acc * invs + (beta[c] - mean[c] * invs);
    __nv_bfloat16 h = __float2bfloat16(y);
    size_t idx = ((size_t)b * CCH + c) * HW + oy * 256 + ox;
    yhi[idx] = h;
    ylo[idx] = __float2bfloat16(y - __bfloat162float(h));
}

// ---------------------------------------------------------------------------
extern "C" void kernel_launch(void* const* d_in, const int* in_sizes, int n_in,
                              void* d_out, int out_size) {
    const float* x          = (const float*)d_in[0];
    const float* qkv_w      = (const float*)d_in[1];
    const float* bias_table = (const float*)d_in[2];
    const float* dw_w       = (const float*)d_in[3];
    const float* bn_gamma   = (const float*)d_in[4];
    const float* bn_beta    = (const float*)d_in[5];
    const float* bn_mean    = (const float*)d_in[6];
    const float* bn_var     = (const float*)d_in[7];
    const float* pw_w       = (const float*)d_in[8];
    float* out = (float*)d_out;

    uint32_t* qkv; cudaGetSymbolAddress((void**)&qkv, g_qkv);
    float* att; cudaGetSymbolAddress((void**)&att, g_att);
    __nv_bfloat16 *xhi, *xlo, *yhi, *ylo, *wqhi, *wqlo, *wphi, *wplo;
    cudaGetSymbolAddress((void**)&xhi, g_xhi);
    cudaGetSymbolAddress((void**)&xlo, g_xlo);
    cudaGetSymbolAddress((void**)&yhi, g_yhi);
    cudaGetSymbolAddress((void**)&ylo, g_ylo);
    cudaGetSymbolAddress((void**)&wqhi, g_wqhi);
    cudaGetSymbolAddress((void**)&wqlo, g_wqlo);
    cudaGetSymbolAddress((void**)&wphi, g_wphi);
    cudaGetSymbolAddress((void**)&wplo, g_wplo);

    cudaFuncSetAttribute(mma_gemm<0>, cudaFuncAttributeMaxDynamicSharedMemorySize, SM_TOT);
    cudaFuncSetAttribute(mma_gemm<1>, cudaFuncAttributeMaxDynamicSharedMemorySize, SM_TOT);

    // 0) bf16 hi/lo splits
    {
        size_t n4 = ((size_t)NB * CCH * HW) / 4;
        split_f32<<<(unsigned)((n4 + 255) / 256), 256>>>(x, xhi, xlo, n4);
        size_t wq4 = (768 * 256) / 4;
        split_f32<<<(unsigned)((wq4 + 255) / 256), 256>>>(qkv_w, wqhi, wqlo, wq4);
        size_t wp4 = (256 * 256) / 4;
        split_f32<<<(unsigned)((wp4 + 255) / 256), 256>>>(pw_w, wphi, wplo, wp4);
    }

    // 1) qkv GEMM -> packed window layout
    mma_gemm<1><<<dim3(768 / 128, HW / 128, NB), 256, SM_TOT>>>(wqhi, wqlo, xhi, xlo, qkv, 768);

    // 2) tensor-core windowed attention + bias + softmax + residual
    attn_mma<<<dim3(2048, 16), 64>>>(qkv, x, bias_table, att);

    // 3) reflect-pad + depthwise 3x3 + BN -> bf16 hi/lo
    dwbn_kernel<<<dim3(8, 32, NB * CCH), dim3(32, 8)>>>(att, dw_w, bn_gamma, bn_beta,
                                                        bn_mean, bn_var, yhi, ylo);

    // 4) pointwise GEMM -> d_out (fp32 channel-major)
    mma_gemm<0><<<dim3(256 / 128, HW / 128, NB), 256, SM_TOT>>>(wphi, wplo, yhi, ylo, out, 256);
}

// round 5
// speedup vs baseline: 2.2892x; 1.1137x over previous
#include <cuda_runtime.h>
#include <cuda_bf16.h>
#include <cstdint>

#define HW 65536       // 256*256
#define CCH 256
#define NB 2

// ---------------------------------------------------------------------------
// Scratch (device globals — no allocations allowed)
// ---------------------------------------------------------------------------
__device__ uint32_t g_qkv[(size_t)NB * 768 * HW];   // packed bf16 hi|lo, window layout
__device__ float g_att[(size_t)NB * CCH * HW];
__device__ __nv_bfloat16 g_xhi[(size_t)NB * CCH * HW];
__device__ __nv_bfloat16 g_xlo[(size_t)NB * CCH * HW];
__device__ __nv_bfloat16 g_yhi[(size_t)NB * CCH * HW];
__device__ __nv_bfloat16 g_ylo[(size_t)NB * CCH * HW];
__device__ __nv_bfloat16 g_wqhi[768 * 256], g_wqlo[768 * 256];
__device__ __nv_bfloat16 g_wphi[256 * 256], g_wplo[256 * 256];

// ---------------------------------------------------------------------------
// PTX helpers (plain sm_80+ PTX)
// ---------------------------------------------------------------------------
__device__ __forceinline__ uint32_t smem_to_u32(const void* p) {
    uint32_t a;
    asm("{ .reg .u64 t; cvta.to.shared.u64 t, %1; cvt.u32.u64 %0, t; }" : "=r"(a) : "l"(p));
    return a;
}
__device__ __forceinline__ void ldsm_x4(uint32_t (&r)[4], uint32_t addr) {
    asm volatile("ldmatrix.sync.aligned.m8n8.x4.shared.b16 {%0,%1,%2,%3}, [%4];"
                 : "=r"(r[0]), "=r"(r[1]), "=r"(r[2]), "=r"(r[3]) : "r"(addr));
}
__device__ __forceinline__ void ldsm_x2_t(uint32_t (&r)[2], uint32_t addr) {
    asm volatile("ldmatrix.sync.aligned.m8n8.x2.trans.shared.b16 {%0,%1}, [%2];"
                 : "=r"(r[0]), "=r"(r[1]) : "r"(addr));
}
__device__ __forceinline__ void mma_bf16(float (&c)[4], const uint32_t (&a)[4],
                                         const uint32_t (&b)[2]) {
    asm volatile("mma.sync.aligned.m16n8k16.row.col.f32.bf16.bf16.f32 "
                 "{%0,%1,%2,%3}, {%4,%5,%6,%7}, {%8,%9}, {%0,%1,%2,%3};"
                 : "+f"(c[0]), "+f"(c[1]), "+f"(c[2]), "+f"(c[3])
                 : "r"(a[0]), "r"(a[1]), "r"(a[2]), "r"(a[3]), "r"(b[0]), "r"(b[1]));
}
__device__ __forceinline__ void cp_async16(uint32_t sm, const void* g) {
    asm volatile("cp.async.cg.shared.global [%0], [%1], 16;" :: "r"(sm), "l"(g));
}
__device__ __forceinline__ uint32_t packsplit(float v) {
    __nv_bfloat16 h = __float2bfloat16(v);
    __nv_bfloat16 l = __float2bfloat16(v - __bfloat162float(h));
    return (uint32_t)__bfloat16_as_ushort(h) | ((uint32_t)__bfloat16_as_ushort(l) << 16);
}

// ---------------------------------------------------------------------------
// fp32 -> bf16 hi/lo split
// ---------------------------------------------------------------------------
__global__ __launch_bounds__(256) void split_f32(const float* __restrict__ in,
                                                 __nv_bfloat16* __restrict__ hi,
                                                 __nv_bfloat16* __restrict__ lo,
                                                 size_t n4) {
    size_t i = (size_t)blockIdx.x * blockDim.x + threadIdx.x;
    if (i >= n4) return;
    float4 v = reinterpret_cast<const float4*>(in)[i];
    __nv_bfloat16 h0 = __float2bfloat16(v.x), h1 = __float2bfloat16(v.y);
    __nv_bfloat16 h2 = __float2bfloat16(v.z), h3 = __float2bfloat16(v.w);
    __nv_bfloat16 l0 = __float2bfloat16(v.x - __bfloat162float(h0));
    __nv_bfloat16 l1 = __float2bfloat16(v.y - __bfloat162float(h1));
    __nv_bfloat16 l2 = __float2bfloat16(v.z - __bfloat162float(h2));
    __nv_bfloat16 l3 = __float2bfloat16(v.w - __bfloat162float(h3));
    reinterpret_cast<__nv_bfloat162*>(hi)[i * 2]     = __nv_bfloat162(h0, h1);
    reinterpret_cast<__nv_bfloat162*>(hi)[i * 2 + 1] = __nv_bfloat162(h2, h3);
    reinterpret_cast<__nv_bfloat162*>(lo)[i * 2]     = __nv_bfloat162(l0, l1);
    reinterpret_cast<__nv_bfloat162*>(lo)[i * 2 + 1] = __nv_bfloat162(l2, l3);
}

// ---------------------------------------------------------------------------
// cp.async 3-stage pipelined split-bf16 tensor-core GEMM.
// MODE 0: write fp32 channel-major.  MODE 1: write packed u32 window layout.
// __launch_bounds__(256, 2): cap regs at 128 so 2 CTAs fit per SM.
// ---------------------------------------------------------------------------
#define SA_STRIDE 80
#define SB_STRIDE 272
#define SA_HI 0
#define SA_LO 10240
#define SB_HI 20480
#define SB_LO 29184
#define STAGE 37888
#define NSTAGE 3
#define SM_TOT (NSTAGE * STAGE)

template<int MODE>
__global__ __launch_bounds__(256, 2) void mma_gemm(const __nv_bfloat16* __restrict__ Whi,
                                                   const __nv_bfloat16* __restrict__ Wlo,
                                                   const __nv_bfloat16* __restrict__ Xhi,
                                                   const __nv_bfloat16* __restrict__ Xlo,
                                                   void* __restrict__ Yv, int Mtot) {
    extern __shared__ __align__(128) char smem[];
    const int tid  = threadIdx.x;
    const int wid  = tid >> 5;
    const int lane = tid & 31;
    const int g    = lane >> 2;
    const int t4   = lane & 3;

    const int oBase = blockIdx.x * 128;
    const int sBase = blockIdx.y * 128;
    const int b     = blockIdx.z;
    const __nv_bfloat16* XhiB = Xhi + (size_t)b * CCH * HW;
    const __nv_bfloat16* XloB = Xlo + (size_t)b * CCH * HW;

    const int wm = (wid >> 2) * 64;
    const int wn = (wid & 3) * 32;
    const uint32_t sb = smem_to_u32(smem);

    const int ar_ = tid >> 2, aq_ = tid & 3;
    const int bk_ = tid >> 4, bq_ = tid & 15;

    float acc[4][4][4];
    #pragma unroll
    for (int mi = 0; mi < 4; mi++)
        #pragma unroll
        for (int ni = 0; ni < 4; ni++)
            #pragma unroll
            for (int q = 0; q < 4; q++) acc[mi][ni][q] = 0.f;

    auto issue = [&](int chunk) {
        const int kc = chunk * 32;
        const uint32_t st = sb + (chunk % NSTAGE) * STAGE;
        #pragma unroll
        for (int p = 0; p < 2; p++) {
            int r = ar_ + p * 64;
            const size_t so = (size_t)(oBase + r) * 256 + kc + aq_ * 8;
            cp_async16(st + SA_HI + r * SA_STRIDE + aq_ * 16, Whi + so);
            cp_async16(st + SA_LO + r * SA_STRIDE + aq_ * 16, Wlo + so);
            int k = bk_ + p * 16;
            const size_t sbo = (size_t)(kc + k) * HW + sBase + bq_ * 8;
            cp_async16(st + SB_HI + k * SB_STRIDE + bq_ * 16, XhiB + sbo);
            cp_async16(st + SB_LO + k * SB_STRIDE + bq_ * 16, XloB + sbo);
        }
        asm volatile("cp.async.commit_group;");
    };

    issue(0);
    issue(1);
    for (int chunk = 0; chunk < 8; chunk++) {
        if (chunk < 6) {
            issue(chunk + 2);
            asm volatile("cp.async.wait_group 2;");
        } else if (chunk == 6) {
            asm volatile("cp.async.wait_group 1;");
        } else {
            asm volatile("cp.async.wait_group 0;");
        }
        __syncthreads();

        const uint32_t smu = sb + (chunk % NSTAGE) * STAGE;
        const int ar    = wm + (lane & 15);
        const int acolq = (lane >> 4) * 8;
        const int brow_base = lane & 15;

        #pragma unroll
        for (int ks = 0; ks < 2; ks++) {
            #pragma unroll
            for (int p = 0; p < 3; p++) {
                const int aOff = (p == 1) ? SA_LO : SA_HI;
                const int bOff = (p == 2) ? SB_LO : SB_HI;
                uint32_t a[4][4];
                const int acol = ks * 16 + acolq;
                #pragma unroll
                for (int mi = 0; mi < 4; mi++)
                    ldsm_x4(a[mi], smu + aOff + (ar + mi * 16) * SA_STRIDE + acol * 2);
                uint32_t bfr[4][2];
                const int brow = ks * 16 + brow_base;
                #pragma unroll
                for (int ni = 0; ni < 4; ni++)
                    ldsm_x2_t(bfr[ni], smu + bOff + brow * SB_STRIDE + (wn + ni * 8) * 2);
                #pragma unroll
                for (int mi = 0; mi < 4; mi++)
                    #pragma unroll
                    for (int ni = 0; ni < 4; ni++)
                        mma_bf16(acc[mi][ni], a[mi], bfr[ni]);
            }
        }
        __syncthreads();
    }

    if (MODE == 0) {
        float* Yb = (float*)Yv + (size_t)b * Mtot * HW;
        #pragma unroll
        for (int mi = 0; mi < 4; mi++) {
            #pragma unroll
            for (int ni = 0; ni < 4; ni++) {
                float* dst0 = Yb + (size_t)(oBase + wm + mi * 16 + g) * HW
                                 + sBase + wn + ni * 8 + t4 * 2;
                *reinterpret_cast<float2*>(dst0) = make_float2(acc[mi][ni][0], acc[mi][ni][1]);
                *reinterpret_cast<float2*>(dst0 + 8 * HW) = make_float2(acc[mi][ni][2], acc[mi][ni][3]);
            }
        }
    } else {
        uint32_t* U = (uint32_t*)Yv;
        #pragma unroll
        for (int mi = 0; mi < 4; mi++) {
            #pragma unroll
            for (int ni = 0; ni < 4; ni++) {
                const int o0   = oBase + wm + mi * 16 + g;
                const int part = o0 >> 8;
                const int head = (o0 >> 4) & 15;
                const int dd   = o0 & 15;
                const int s0   = sBase + wn + ni * 8 + t4 * 2;
                const int y    = s0 >> 8, xx = s0 & 255;
                const int win  = b * 1024 + (y >> 3) * 32 + (xx >> 3);
                const int tok  = (y & 7) * 8 + (xx & 7);
                const size_t base = ((size_t)(win * 3 + part) * 16 + head) * 1024 + tok;
                uint2 v0 = make_uint2(packsplit(acc[mi][ni][0]), packsplit(acc[mi][ni][1]));
                uint2 v1 = make_uint2(packsplit(acc[mi][ni][2]), packsplit(acc[mi][ni][3]));
                *reinterpret_cast<uint2*>(U + base + (size_t)dd * 64)       = v0;
                *reinterpret_cast<uint2*>(U + base + (size_t)(dd + 8) * 64) = v1;
            }
        }
    }
}

// ---------------------------------------------------------------------------
// Tensor-core window attention.  One block = one (window, head), 2 warps.
// qkv packed u32 (hi|lo<<16), layout [win][part][head][d(16)][tok(64)].
// ---------------------------------------------------------------------------
__global__ __launch_bounds__(64) void attn_mma(const uint32_t* __restrict__ qkvU,
                                               const float* __restrict__ x,
                                               const float* __restrict__ bias_table,
                                               float* __restrict__ att) {
    const int win = blockIdx.x;
    const int h   = blockIdx.y;
    const int tid = threadIdx.x;
    const int w   = tid >> 5;
    const int lane = tid & 31;
    const int g = lane >> 2, t = lane & 3;

    __shared__ float bs[225];
    for (int i = tid; i < 225; i += 64) bs[i] = bias_table[i * 16 + h];
    __syncthreads();

    const uint32_t* Q = qkvU + ((size_t)(win * 3) * 16 + h) * 1024;
    const uint32_t* K = Q + 16 * 1024;
    const uint32_t* V = Q + 32 * 1024;

    uint32_t ahi[2][4], alo[2][4];
    #pragma unroll
    for (int mi = 0; mi < 2; mi++) {
        const int tokm = w * 32 + mi * 16;
        #pragma unroll
        for (int r = 0; r < 4; r++) {
            const int m  = tokm + g + ((r & 1) ? 8 : 0);
            const int k0 = t * 2 + ((r >= 2) ? 8 : 0);
            uint32_t u0 = Q[k0 * 64 + m];
            uint32_t u1 = Q[(k0 + 1) * 64 + m];
            ahi[mi][r] = __byte_perm(u0, u1, 0x5410);
            alo[mi][r] = __byte_perm(u0, u1, 0x7632);
        }
    }
    uint32_t bhi[8][2], blo[8][2];
    #pragma unroll
    for (int ni = 0; ni < 8; ni++) {
        const int n = ni * 8 + g;
        #pragma unroll
        for (int r = 0; r < 2; r++) {
            const int k0 = t * 2 + r * 8;
            uint32_t u0 = K[k0 * 64 + n];
            uint32_t u1 = K[(k0 + 1) * 64 + n];
            bhi[ni][r] = __byte_perm(u0, u1, 0x5410);
            blo[ni][r] = __byte_perm(u0, u1, 0x7632);
        }
    }

    float C[2][8][4];
    #pragma unroll
    for (int mi = 0; mi < 2; mi++)
        #pragma unroll
        for (int ni = 0; ni < 8; ni++) {
            C[mi][ni][0] = C[mi][ni][1] = C[mi][ni][2] = C[mi][ni][3] = 0.f;
            mma_bf16(C[mi][ni], ahi[mi], bhi[ni]);
            mma_bf16(C[mi][ni], alo[mi], bhi[ni]);
            mma_bf16(C[mi][ni], ahi[mi], blo[ni]);
        }

    #pragma unroll
    for (int mi = 0; mi < 2; mi++) {
        const int yl0 = w * 4 + mi * 2;
        float m0 = -1e30f, m1 = -1e30f;
        #pragma unroll
        for (int ni = 0; ni < 8; ni++) {
            const int cb0 = g - t * 2 + 7;
            C[mi][ni][0] = C[mi][ni][0] * 0.25f + bs[(yl0 - ni + 7) * 15 + cb0];
            C[mi][ni][1] = C[mi][ni][1] * 0.25f + bs[(yl0 - ni + 7) * 15 + cb0 - 1];
            C[mi][ni][2] = C[mi][ni][2] * 0.25f + bs[(yl0 + 1 - ni + 7) * 15 + cb0];
            C[mi][ni][3] = C[mi][ni][3] * 0.25f + bs[(yl0 + 1 - ni + 7) * 15 + cb0 - 1];
            m0 = fmaxf(m0, fmaxf(C[mi][ni][0], C[mi][ni][1]));
            m1 = fmaxf(m1, fmaxf(C[mi][ni][2], C[mi][ni][3]));
        }
        m0 = fmaxf(m0, __shfl_xor_sync(0xffffffffu, m0, 1));
        m0 = fmaxf(m0, __shfl_xor_sync(0xffffffffu, m0, 2));
        m1 = fmaxf(m1, __shfl_xor_sync(0xffffffffu, m1, 1));
        m1 = fmaxf(m1, __shfl_xor_sync(0xffffffffu, m1, 2));
        float s0 = 0.f, s1 = 0.f;
        #pragma unroll
        for (int ni = 0; ni < 8; ni++) {
            C[mi][ni][0] = __expf(C[mi][ni][0] - m0);
            C[mi][ni][1] = __expf(C[mi][ni][1] - m0);
            C[mi][ni][2] = __expf(C[mi][ni][2] - m1);
            C[mi][ni][3] = __expf(C[mi][ni][3] - m1);
            s0 += C[mi][ni][0] + C[mi][ni][1];
            s1 += C[mi][ni][2] + C[mi][ni][3];
        }
        s0 += __shfl_xor_sync(0xffffffffu, s0, 1);
        s0 += __shfl_xor_sync(0xffffffffu, s0, 2);
        s1 += __shfl_xor_sync(0xffffffffu, s1, 1);
        s1 += __shfl_xor_sync(0xffffffffu, s1, 2);
        const float iv0 = 1.f / s0, iv1 = 1.f / s1;
        #pragma unroll
        for (int ni = 0; ni < 8; ni++) {
            C[mi][ni][0] *= iv0; C[mi][ni][1] *= iv0;
            C[mi][ni][2] *= iv1; C[mi][ni][3] *= iv1;
        }
    }

    float O[2][2][4];
    #pragma unroll
    for (int mi = 0; mi < 2; mi++)
        #pragma unroll
        for (int nd = 0; nd < 2; nd++)
            O[mi][nd][0] = O[mi][nd][1] = O[mi][nd][2] = O[mi][nd][3] = 0.f;

    #pragma unroll
    for (int kk = 0; kk < 4; kk++) {
        uint32_t vhi[2][2], vlo[2][2];
        #pragma unroll
        for (int nd = 0; nd < 2; nd++)
            #pragma unroll
            for (int r = 0; r < 2; r++) {
                const uint32_t* vp = V + (nd * 8 + g) * 64 + kk * 16 + t * 2 + r * 8;
                uint32_t u0 = vp[0], u1 = vp[1];
                vhi[nd][r] = __byte_perm(u0, u1, 0x5410);
                vlo[nd][r] = __byte_perm(u0, u1, 0x7632);
            }
        #pragma unroll
        for (int mi = 0; mi < 2; mi++) {
            uint32_t phi[4], plo[4];
            #pragma unroll
            for (int r = 0; r < 4; r++) {
                const int ni = 2 * kk + (r >> 1);
                const float e  = C[mi][ni][(r & 1) * 2];
                const float o_ = C[mi][ni][(r & 1) * 2 + 1];
                uint32_t hp;
                asm("cvt.rn.bf16x2.f32 %0, %1, %2;" : "=r"(hp) : "f"(o_), "f"(e));
                const float eh = __uint_as_float((hp & 0xFFFFu) << 16);
                const float oh = __uint_as_float(hp & 0xFFFF0000u);
                uint32_t lp;
                asm("cvt.rn.bf16x2.f32 %0, %1, %2;" : "=r"(lp) : "f"(o_ - oh), "f"(e - eh));
                phi[r] = hp; plo[r] = lp;
            }
            #pragma unroll
            for (int nd = 0; nd < 2; nd++) {
                mma_bf16(O[mi][nd], phi, vhi[nd]);
                mma_bf16(O[mi][nd], plo, vhi[nd]);
                mma_bf16(O[mi][nd], phi, vlo[nd]);
            }
        }
    }

    const int bW = win >> 10, loc = win & 1023;
    const int wy = loc >> 5, wx = loc & 31;
    #pragma unroll
    for (int mi = 0; mi < 2; mi++) {
        const int row0 = w * 4 + mi * 2;
        const int sp0 = (wy * 8 + row0) * 256 + wx * 8 + g;
        const int sp1 = sp0 + 256;
        #pragma unroll
        for (int nd = 0; nd < 2; nd++) {
            const int d0 = nd * 8 + t * 2;
            const size_t c0 = ((size_t)bW * 256 + h * 16 + d0) * HW;
            const size_t c1 = c0 + HW;
            att[c0 + sp0] = O[mi][nd][0] + x[c0 + sp0];
            att[c1 + sp0] = O[mi][nd][1] + x[c1 + sp0];
            att[c0 + sp1] = O[mi][nd][2] + x[c0 + sp1];
            att[c1 + sp1] = O[mi][nd][3] + x[c1 + sp1];
        }
    }
}

// ---------------------------------------------------------------------------
// reflect-pad -> depthwise 3x3 -> BN -> bf16 hi/lo
// ---------------------------------------------------------------------------
__global__ __launch_bounds__(256) void dwbn_kernel(const float* __restrict__ att,
                                                   const float* __restrict__ dw_w,
                                                   const float* __restrict__ gamma,
                                                   const float* __restrict__ beta,
                                                   const float* __restrict__ mean,
                                                   const float* __restrict__ var,
                                                   __nv_bfloat16* __restrict__ yhi,
                                                   __nv_bfloat16* __restrict__ ylo) {
    const int c  = blockIdx.z & 255;
    const int b  = blockIdx.z >> 8;
    const int ox = blockIdx.x * 32 + threadIdx.x;
    const int oy = blockIdx.y * 8 + threadIdx.y;

    const float* in = att + ((size_t)b * CCH + c) * HW;
    float w[9];
    #pragma unroll
    for (int tt = 0; tt < 9; tt++) w[tt] = dw_w[c * 9 + tt];

    float acc = 0.f;
    #pragma unroll
    for (int di = 0; di < 3; di++) {
        int r = oy + di - 1;
        if (r < 0) continue;
        if (r == 256) r = 254;
        #pragma unroll
        for (int dj = 0; dj < 3; dj++) {
            int cc = ox + dj - 1;
            if (cc < 0) continue;
            if (cc == 256) cc = 254;
            acc += w[di * 3 + dj] * __ldg(&in[r * 256 + cc]);
        }
    }
    const float invs = gamma[c] * rsqrtf(var[c] + 1e-5f);
    float y = acc * invs + (beta[c] - mean[c] * invs);
    __nv_bfloat16 h = __float2bfloat16(y);
    size_t idx = ((size_t)b * CCH + c) * HW + oy * 256 + ox;
    yhi[idx] = h;
    ylo[idx] = __float2bfloat16(y - __bfloat162float(h));
}

// ---------------------------------------------------------------------------
extern "C" void kernel_launch(void* const* d_in, const int* in_sizes, int n_in,
                              void* d_out, int out_size) {
    const float* x          = (const float*)d_in[0];
    const float* qkv_w      = (const float*)d_in[1];
    const float* bias_table = (const float*)d_in[2];
    const float* dw_w       = (const float*)d_in[3];
    const float* bn_gamma   = (const float*)d_in[4];
    const float* bn_beta    = (const float*)d_in[5];
    const float* bn_mean    = (const float*)d_in[6];
    const float* bn_var     = (const float*)d_in[7];
    const float* pw_w       = (const float*)d_in[8];
    float* out = (float*)d_out;

    uint32_t* qkv; cudaGetSymbolAddress((void**)&qkv, g_qkv);
    float* att; cudaGetSymbolAddress((void**)&att, g_att);
    __nv_bfloat16 *xhi, *xlo, *yhi, *ylo, *wqhi, *wqlo, *wphi, *wplo;
    cudaGetSymbolAddress((void**)&xhi, g_xhi);
    cudaGetSymbolAddress((void**)&xlo, g_xlo);
    cudaGetSymbolAddress((void**)&yhi, g_yhi);
    cudaGetSymbolAddress((void**)&ylo, g_ylo);
    cudaGetSymbolAddress((void**)&wqhi, g_wqhi);
    cudaGetSymbolAddress((void**)&wqlo, g_wqlo);
    cudaGetSymbolAddress((void**)&wphi, g_wphi);
    cudaGetSymbolAddress((void**)&wplo, g_wplo);

    cudaFuncSetAttribute(mma_gemm<0>, cudaFuncAttributeMaxDynamicSharedMemorySize, SM_TOT);
    cudaFuncSetAttribute(mma_gemm<1>, cudaFuncAttributeMaxDynamicSharedMemorySize, SM_TOT);

    // 0) bf16 hi/lo splits
    {
        size_t n4 = ((size_t)NB * CCH * HW) / 4;
        split_f32<<<(unsigned)((n4 + 255) / 256), 256>>>(x, xhi, xlo, n4);
        size_t wq4 = (768 * 256) / 4;
        split_f32<<<(unsigned)((wq4 + 255) / 256), 256>>>(qkv_w, wqhi, wqlo, wq4);
        size_t wp4 = (256 * 256) / 4;
        split_f32<<<(unsigned)((wp4 + 255) / 256), 256>>>(pw_w, wphi, wplo, wp4);
    }

    // 1) qkv GEMM -> packed window layout
    mma_gemm<1><<<dim3(768 / 128, HW / 128, NB), 256, SM_TOT>>>(wqhi, wqlo, xhi, xlo, qkv, 768);

    // 2) tensor-core windowed attention + bias + softmax + residual
    attn_mma<<<dim3(2048, 16), 64>>>(qkv, x, bias_table, att);

    // 3) reflect-pad + depthwise 3x3 + BN -> bf16 hi/lo
    dwbn_kernel<<<dim3(8, 32, NB * CCH), dim3(32, 8)>>>(att, dw_w, bn_gamma, bn_beta,
                                                        bn_mean, bn_var, yhi, ylo);

    // 4) pointwise GEMM -> d_out (fp32 channel-major)
    mma_gemm<0><<<dim3(256 / 128, HW / 128, NB), 256, SM_TOT>>>(wphi, wplo, yhi, ylo, out, 256);
}

// round 6
// speedup vs baseline: 3.6120x; 1.5778x over previous
#include <cuda_runtime.h>
#include <cuda_fp16.h>
#include <cstdint>

#define HW 65536       // 256*256
#define CCH 256
#define NB 2

// ---------------------------------------------------------------------------
// Scratch (device globals — no allocations allowed)
// ---------------------------------------------------------------------------
__device__ __half g_qkv[(size_t)NB * 768 * HW];   // fp16, window layout [win][part][head][d][tok]
__device__ float  g_att[(size_t)NB * CCH * HW];
__device__ __half g_xh [(size_t)NB * CCH * HW];
__device__ __half g_yh [(size_t)NB * CCH * HW];
__device__ __half g_wq [768 * 256];
__device__ __half g_wp [256 * 256];

// ---------------------------------------------------------------------------
// PTX helpers (plain sm_80+ PTX)
// ---------------------------------------------------------------------------
__device__ __forceinline__ uint32_t smem_to_u32(const void* p) {
    uint32_t a;
    asm("{ .reg .u64 t; cvta.to.shared.u64 t, %1; cvt.u32.u64 %0, t; }" : "=r"(a) : "l"(p));
    return a;
}
__device__ __forceinline__ void ldsm_x4(uint32_t (&r)[4], uint32_t addr) {
    asm volatile("ldmatrix.sync.aligned.m8n8.x4.shared.b16 {%0,%1,%2,%3}, [%4];"
                 : "=r"(r[0]), "=r"(r[1]), "=r"(r[2]), "=r"(r[3]) : "r"(addr));
}
__device__ __forceinline__ void ldsm_x2_t(uint32_t (&r)[2], uint32_t addr) {
    asm volatile("ldmatrix.sync.aligned.m8n8.x2.trans.shared.b16 {%0,%1}, [%2];"
                 : "=r"(r[0]), "=r"(r[1]) : "r"(addr));
}
__device__ __forceinline__ void mma_f16(float (&c)[4], const uint32_t (&a)[4],
                                        const uint32_t (&b)[2]) {
    asm volatile("mma.sync.aligned.m16n8k16.row.col.f32.f16.f16.f32 "
                 "{%0,%1,%2,%3}, {%4,%5,%6,%7}, {%8,%9}, {%0,%1,%2,%3};"
                 : "+f"(c[0]), "+f"(c[1]), "+f"(c[2]), "+f"(c[3])
                 : "r"(a[0]), "r"(a[1]), "r"(a[2]), "r"(a[3]), "r"(b[0]), "r"(b[1]));
}
__device__ __forceinline__ void cp_async16(uint32_t sm, const void* g) {
    asm volatile("cp.async.cg.shared.global [%0], [%1], 16;" :: "r"(sm), "l"(g));
}

// ---------------------------------------------------------------------------
// fp32 -> fp16 convert (vectorized by 4)
// ---------------------------------------------------------------------------
__global__ __launch_bounds__(256) void cvt_f16(const float* __restrict__ in,
                                               __half* __restrict__ out, size_t n4) {
    size_t i = (size_t)blockIdx.x * blockDim.x + threadIdx.x;
    if (i >= n4) return;
    float4 v = reinterpret_cast<const float4*>(in)[i];
    __half2 h0 = __floats2half2_rn(v.x, v.y);
    __half2 h1 = __floats2half2_rn(v.z, v.w);
    reinterpret_cast<__half2*>(out)[i * 2]     = h0;
    reinterpret_cast<__half2*>(out)[i * 2 + 1] = h1;
}

// ---------------------------------------------------------------------------
// cp.async 4-stage pipelined fp16 tensor-core GEMM.
// MODE 0: write fp32 channel-major.  MODE 1: write fp16 window layout.
// ---------------------------------------------------------------------------
#define SA_STRIDE 80      // 32 halfs (64B) padded
#define SB_STRIDE 272     // 128 halfs (256B) padded
#define SA_OFF 0
#define SB_OFF 10240      // 128*80
#define STAGE 18944       // 10240 + 32*272
#define NSTAGE 4
#define SM_TOT (NSTAGE * STAGE)

template<int MODE>
__global__ __launch_bounds__(256, 2) void mma_gemm(const __half* __restrict__ Wm,
                                                   const __half* __restrict__ X,
                                                   void* __restrict__ Yv, int Mtot) {
    extern __shared__ __align__(128) char smem[];
    const int tid  = threadIdx.x;
    const int wid  = tid >> 5;
    const int lane = tid & 31;
    const int g    = lane >> 2;
    const int t4   = lane & 3;

    const int oBase = blockIdx.x * 128;
    const int sBase = blockIdx.y * 128;
    const int b     = blockIdx.z;
    const __half* Xb = X + (size_t)b * CCH * HW;

    const int wm = (wid >> 2) * 64;
    const int wn = (wid & 3) * 32;
    const uint32_t sb = smem_to_u32(smem);

    const int ar_ = tid >> 2, aq_ = tid & 3;
    const int bk_ = tid >> 4, bq_ = tid & 15;

    float acc[4][4][4];
    #pragma unroll
    for (int mi = 0; mi < 4; mi++)
        #pragma unroll
        for (int ni = 0; ni < 4; ni++)
            #pragma unroll
            for (int q = 0; q < 4; q++) acc[mi][ni][q] = 0.f;

    auto issue = [&](int chunk) {
        const int kc = chunk * 32;
        const uint32_t st = sb + (chunk & 3) * STAGE;
        #pragma unroll
        for (int p = 0; p < 2; p++) {
            int r = ar_ + p * 64;
            cp_async16(st + SA_OFF + r * SA_STRIDE + aq_ * 16,
                       Wm + (size_t)(oBase + r) * 256 + kc + aq_ * 8);
            int k = bk_ + p * 16;
            cp_async16(st + SB_OFF + k * SB_STRIDE + bq_ * 16,
                       Xb + (size_t)(kc + k) * HW + sBase + bq_ * 8);
        }
        asm volatile("cp.async.commit_group;");
    };

    issue(0); issue(1); issue(2);
    for (int chunk = 0; chunk < 8; chunk++) {
        if (chunk < 5) {
            issue(chunk + 3);
            asm volatile("cp.async.wait_group 3;");
        } else if (chunk == 5) {
            asm volatile("cp.async.wait_group 2;");
        } else if (chunk == 6) {
            asm volatile("cp.async.wait_group 1;");
        } else {
            asm volatile("cp.async.wait_group 0;");
        }
        __syncthreads();

        const uint32_t smu = sb + (chunk & 3) * STAGE;
        const int ar    = wm + (lane & 15);
        const int acolq = (lane >> 4) * 8;
        const int brow_base = lane & 15;

        #pragma unroll
        for (int ks = 0; ks < 2; ks++) {
            uint32_t a[4][4];
            const int acol = ks * 16 + acolq;
            #pragma unroll
            for (int mi = 0; mi < 4; mi++)
                ldsm_x4(a[mi], smu + SA_OFF + (ar + mi * 16) * SA_STRIDE + acol * 2);
            uint32_t bfr[4][2];
            const int brow = ks * 16 + brow_base;
            #pragma unroll
            for (int ni = 0; ni < 4; ni++)
                ldsm_x2_t(bfr[ni], smu + SB_OFF + brow * SB_STRIDE + (wn + ni * 8) * 2);
            #pragma unroll
            for (int mi = 0; mi < 4; mi++)
                #pragma unroll
                for (int ni = 0; ni < 4; ni++)
                    mma_f16(acc[mi][ni], a[mi], bfr[ni]);
        }
        __syncthreads();
    }

    if (MODE == 0) {
        float* Yb = (float*)Yv + (size_t)b * Mtot * HW;
        #pragma unroll
        for (int mi = 0; mi < 4; mi++) {
            #pragma unroll
            for (int ni = 0; ni < 4; ni++) {
                float* dst0 = Yb + (size_t)(oBase + wm + mi * 16 + g) * HW
                                 + sBase + wn + ni * 8 + t4 * 2;
                *reinterpret_cast<float2*>(dst0) = make_float2(acc[mi][ni][0], acc[mi][ni][1]);
                *reinterpret_cast<float2*>(dst0 + 8 * HW) = make_float2(acc[mi][ni][2], acc[mi][ni][3]);
            }
        }
    } else {
        __half* U = (__half*)Yv;
        #pragma unroll
        for (int mi = 0; mi < 4; mi++) {
            #pragma unroll
            for (int ni = 0; ni < 4; ni++) {
                const int o0   = oBase + wm + mi * 16 + g;
                const int part = o0 >> 8;
                const int head = (o0 >> 4) & 15;
                const int dd   = o0 & 15;
                const int s0   = sBase + wn + ni * 8 + t4 * 2;
                const int y    = s0 >> 8, xx = s0 & 255;
                const int win  = b * 1024 + (y >> 3) * 32 + (xx >> 3);
                const int tok  = (y & 7) * 8 + (xx & 7);
                const size_t base = ((size_t)(win * 3 + part) * 16 + head) * 1024 + tok;
                *reinterpret_cast<__half2*>(U + base + (size_t)dd * 64) =
                    __floats2half2_rn(acc[mi][ni][0], acc[mi][ni][1]);
                *reinterpret_cast<__half2*>(U + base + (size_t)(dd + 8) * 64) =
                    __floats2half2_rn(acc[mi][ni][2], acc[mi][ni][3]);
            }
        }
    }
}

// ---------------------------------------------------------------------------
// Tensor-core window attention (fp16).  One block = one (window, head), 2 warps.
// qkv layout: [win][part][head][d(16)][tok(64)] fp16.
// ---------------------------------------------------------------------------
__global__ __launch_bounds__(64) void attn_mma(const __half* __restrict__ qkvH,
                                               const float* __restrict__ x,
                                               const float* __restrict__ bias_table,
                                               float* __restrict__ att) {
    const int win = blockIdx.x;
    const int h   = blockIdx.y;
    const int tid = threadIdx.x;
    const int w   = tid >> 5;
    const int lane = tid & 31;
    const int g = lane >> 2, t = lane & 3;

    __shared__ float bs[225];
    for (int i = tid; i < 225; i += 64) bs[i] = bias_table[i * 16 + h];
    __syncthreads();

    const uint32_t* Q32 = (const uint32_t*)(qkvH + ((size_t)(win * 3) * 16 + h) * 1024);
    const uint32_t* K32 = Q32 + 16 * 512;
    const uint32_t* V32 = Q32 + 32 * 512;

    // ---- Q A-fragments: thread needs halfs (k0, k0+1) at token-row m ----
    uint32_t afr[2][4];
    #pragma unroll
    for (int mi = 0; mi < 2; mi++) {
        const int tokm = w * 32 + mi * 16;
        #pragma unroll
        for (int r = 0; r < 4; r++) {
            const int m  = tokm + g + ((r & 1) ? 8 : 0);
            const int k0 = t * 2 + ((r >= 2) ? 8 : 0);
            uint32_t u0 = Q32[k0 * 32 + (m >> 1)];
            uint32_t u1 = Q32[(k0 + 1) * 32 + (m >> 1)];
            afr[mi][r] = __byte_perm(u0, u1, (m & 1) ? 0x7632 : 0x5410);
        }
    }
    // ---- K B-fragments ----
    uint32_t bfr[8][2];
    #pragma unroll
    for (int ni = 0; ni < 8; ni++) {
        const int n = ni * 8 + g;
        #pragma unroll
        for (int r = 0; r < 2; r++) {
            const int k0 = t * 2 + r * 8;
            uint32_t u0 = K32[k0 * 32 + (n >> 1)];
            uint32_t u1 = K32[(k0 + 1) * 32 + (n >> 1)];
            bfr[ni][r] = __byte_perm(u0, u1, (n & 1) ? 0x7632 : 0x5410);
        }
    }

    // ---- QK^T ----
    float C[2][8][4];
    #pragma unroll
    for (int mi = 0; mi < 2; mi++)
        #pragma unroll
        for (int ni = 0; ni < 8; ni++) {
            C[mi][ni][0] = C[mi][ni][1] = C[mi][ni][2] = C[mi][ni][3] = 0.f;
            mma_f16(C[mi][ni], afr[mi], bfr[ni]);
        }

    // ---- scale + bias + softmax ----
    #pragma unroll
    for (int mi = 0; mi < 2; mi++) {
        const int yl0 = w * 4 + mi * 2;
        float m0 = -1e30f, m1 = -1e30f;
        #pragma unroll
        for (int ni = 0; ni < 8; ni++) {
            const int cb0 = g - t * 2 + 7;
            C[mi][ni][0] = C[mi][ni][0] * 0.25f + bs[(yl0 - ni + 7) * 15 + cb0];
            C[mi][ni][1] = C[mi][ni][1] * 0.25f + bs[(yl0 - ni + 7) * 15 + cb0 - 1];
            C[mi][ni][2] = C[mi][ni][2] * 0.25f + bs[(yl0 + 1 - ni + 7) * 15 + cb0];
            C[mi][ni][3] = C[mi][ni][3] * 0.25f + bs[(yl0 + 1 - ni + 7) * 15 + cb0 - 1];
            m0 = fmaxf(m0, fmaxf(C[mi][ni][0], C[mi][ni][1]));
            m1 = fmaxf(m1, fmaxf(C[mi][ni][2], C[mi][ni][3]));
        }
        m0 = fmaxf(m0, __shfl_xor_sync(0xffffffffu, m0, 1));
        m0 = fmaxf(m0, __shfl_xor_sync(0xffffffffu, m0, 2));
        m1 = fmaxf(m1, __shfl_xor_sync(0xffffffffu, m1, 1));
        m1 = fmaxf(m1, __shfl_xor_sync(0xffffffffu, m1, 2));
        float s0 = 0.f, s1 = 0.f;
        #pragma unroll
        for (int ni = 0; ni < 8; ni++) {
            C[mi][ni][0] = __expf(C[mi][ni][0] - m0);
            C[mi][ni][1] = __expf(C[mi][ni][1] - m0);
            C[mi][ni][2] = __expf(C[mi][ni][2] - m1);
            C[mi][ni][3] = __expf(C[mi][ni][3] - m1);
            s0 += C[mi][ni][0] + C[mi][ni][1];
            s1 += C[mi][ni][2] + C[mi][ni][3];
        }
        s0 += __shfl_xor_sync(0xffffffffu, s0, 1);
        s0 += __shfl_xor_sync(0xffffffffu, s0, 2);
        s1 += __shfl_xor_sync(0xffffffffu, s1, 1);
        s1 += __shfl_xor_sync(0xffffffffu, s1, 2);
        const float iv0 = 1.f / s0, iv1 = 1.f / s1;
        #pragma unroll
        for (int ni = 0; ni < 8; ni++) {
            C[mi][ni][0] *= iv0; C[mi][ni][1] *= iv0;
            C[mi][ni][2] *= iv1; C[mi][ni][3] *= iv1;
        }
    }

    // ---- P @ V ----
    float O[2][2][4];
    #pragma unroll
    for (int mi = 0; mi < 2; mi++)
        #pragma unroll
        for (int nd = 0; nd < 2; nd++)
            O[mi][nd][0] = O[mi][nd][1] = O[mi][nd][2] = O[mi][nd][3] = 0.f;

    #pragma unroll
    for (int kk = 0; kk < 4; kk++) {
        uint32_t vfr[2][2];
        #pragma unroll
        for (int nd = 0; nd < 2; nd++)
            #pragma unroll
            for (int r = 0; r < 2; r++)
                vfr[nd][r] = V32[(nd * 8 + g) * 32 + kk * 8 + t + r * 4];
        #pragma unroll
        for (int mi = 0; mi < 2; mi++) {
            uint32_t pfr[4];
            #pragma unroll
            for (int r = 0; r < 4; r++) {
                const int ni = 2 * kk + (r >> 1);
                const float e  = C[mi][ni][(r & 1) * 2];
                const float o_ = C[mi][ni][(r & 1) * 2 + 1];
                asm("cvt.rn.f16x2.f32 %0, %1, %2;" : "=r"(pfr[r]) : "f"(o_), "f"(e));
            }
            #pragma unroll
            for (int nd = 0; nd < 2; nd++)
                mma_f16(O[mi][nd], pfr, vfr[nd]);
        }
    }

    // ---- residual + store to channel-major fp32 ----
    const int bW = win >> 10, loc = win & 1023;
    const int wy = loc >> 5, wx = loc & 31;
    #pragma unroll
    for (int mi = 0; mi < 2; mi++) {
        const int row0 = w * 4 + mi * 2;
        const int sp0 = (wy * 8 + row0) * 256 + wx * 8 + g;
        const int sp1 = sp0 + 256;
        #pragma unroll
        for (int nd = 0; nd < 2; nd++) {
            const int d0 = nd * 8 + t * 2;
            const size_t c0 = ((size_t)bW * 256 + h * 16 + d0) * HW;
            const size_t c1 = c0 + HW;
            att[c0 + sp0] = O[mi][nd][0] + x[c0 + sp0];
            att[c1 + sp0] = O[mi][nd][1] + x[c1 + sp0];
            att[c0 + sp1] = O[mi][nd][2] + x[c0 + sp1];
            att[c1 + sp1] = O[mi][nd][3] + x[c1 + sp1];
        }
    }
}

// ---------------------------------------------------------------------------
// reflect-pad -> depthwise 3x3 -> BN -> fp16
// ---------------------------------------------------------------------------
__global__ __launch_bounds__(256) void dwbn_kernel(const float* __restrict__ att,
                                                   const float* __restrict__ dw_w,
                                                   const float* __restrict__ gamma,
                                                   const float* __restrict__ beta,
                                                   const float* __restrict__ mean,
                                                   const float* __restrict__ var,
                                                   __half* __restrict__ yh) {
    const int c  = blockIdx.z & 255;
    const int b  = blockIdx.z >> 8;
    const int ox = blockIdx.x * 32 + threadIdx.x;
    const int oy = blockIdx.y * 8 + threadIdx.y;

    const float* in = att + ((size_t)b * CCH + c) * HW;
    float w[9];
    #pragma unroll
    for (int tt = 0; tt < 9; tt++) w[tt] = dw_w[c * 9 + tt];

    float acc = 0.f;
    #pragma unroll
    for (int di = 0; di < 3; di++) {
        int r = oy + di - 1;
        if (r < 0) continue;
        if (r == 256) r = 254;
        #pragma unroll
        for (int dj = 0; dj < 3; dj++) {
            int cc = ox + dj - 1;
            if (cc < 0) continue;
            if (cc == 256) cc = 254;
            acc += w[di * 3 + dj] * __ldg(&in[r * 256 + cc]);
        }
    }
    const float invs = gamma[c] * rsqrtf(var[c] + 1e-5f);
    float y = acc * invs + (beta[c] - mean[c] * invs);
    yh[((size_t)b * CCH + c) * HW + oy * 256 + ox] = __float2half(y);
}

// ---------------------------------------------------------------------------
extern "C" void kernel_launch(void* const* d_in, const int* in_sizes, int n_in,
                              void* d_out, int out_size) {
    const float* x          = (const float*)d_in[0];
    const float* qkv_w      = (const float*)d_in[1];
    const float* bias_table = (const float*)d_in[2];
    const float* dw_w       = (const float*)d_in[3];
    const float* bn_gamma   = (const float*)d_in[4];
    const float* bn_beta    = (const float*)d_in[5];
    const float* bn_mean    = (const float*)d_in[6];
    const float* bn_var     = (const float*)d_in[7];
    const float* pw_w       = (const float*)d_in[8];
    float* out = (float*)d_out;

    __half* qkv; cudaGetSymbolAddress((void**)&qkv, g_qkv);
    float* att;  cudaGetSymbolAddress((void**)&att, g_att);
    __half *xh, *yh, *wq, *wp;
    cudaGetSymbolAddress((void**)&xh, g_xh);
    cudaGetSymbolAddress((void**)&yh, g_yh);
    cudaGetSymbolAddress((void**)&wq, g_wq);
    cudaGetSymbolAddress((void**)&wp, g_wp);

    cudaFuncSetAttribute(mma_gemm<0>, cudaFuncAttributeMaxDynamicSharedMemorySize, SM_TOT);
    cudaFuncSetAttribute(mma_gemm<1>, cudaFuncAttributeMaxDynamicSharedMemorySize, SM_TOT);

    // 0) fp16 conversions
    {
        size_t n4 = ((size_t)NB * CCH * HW) / 4;
        cvt_f16<<<(unsigned)((n4 + 255) / 256), 256>>>(x, xh, n4);
        cvt_f16<<<(768 * 256 / 4 + 255) / 256, 256>>>(qkv_w, wq, 768 * 256 / 4);
        cvt_f16<<<(256 * 256 / 4 + 255) / 256, 256>>>(pw_w, wp, 256 * 256 / 4);
    }

    // 1) qkv GEMM -> fp16 window layout
    mma_gemm<1><<<dim3(768 / 128, HW / 128, NB), 256, SM_TOT>>>(wq, xh, qkv, 768);

    // 2) tensor-core windowed attention + bias + softmax + residual
    attn_mma<<<dim3(2048, 16), 64>>>(qkv, x, bias_table, att);

    // 3) reflect-pad + depthwise 3x3 + BN -> fp16
    dwbn_kernel<<<dim3(8, 32, NB * CCH), dim3(32, 8)>>>(att, dw_w, bn_gamma, bn_beta,
                                                        bn_mean, bn_var, yh);

    // 4) pointwise GEMM -> d_out (fp32 channel-major)
    mma_gemm<0><<<dim3(256 / 128, HW / 128, NB), 256, SM_TOT>>>(wp, yh, out, 256);
}